// round 2
// baseline (speedup 1.0000x reference)
#include <cuda_runtime.h>
#include <cstdint>

// ---------------- problem constants ----------------
namespace {
constexpr int B    = 2;
constexpr int C0   = 64;
constexpr int C1   = 128;
constexpr int H    = 128, W = 128;
constexpr int HW   = H * W;            // 16384
constexpr int NPIX = B * HW;           // 32768
constexpr int R2   = 256;              // 16x16 reduced K/V
constexpr int DH   = 32;               // dim_head
constexpr float BN_EPS = 1e-5f;
}

// ---------------- scratch (static device, no allocs) ----------------
__device__ float g_pool[B * C0 * HW];
__device__ float g_t   [B * C1 * HW];
__device__ float g_u   [B * C1 * HW];
__device__ float g_o   [B * C1 * HW];
__device__ float g_qkv [B * 3 * C1 * HW];
__device__ float g_kd  [B * C1 * R2];
__device__ float g_vd  [B * C1 * R2];
__device__ float g_A   [8 * 128];            // per-channel BN scale, slotted
__device__ float g_Bv  [8 * 128];            // per-channel BN shift, slotted

// ---------------- maxpool 2x2 (256x256 -> 128x128) ----------------
__global__ void k_maxpool(const float* __restrict__ x, float* __restrict__ out) {
    int i = blockIdx.x * 256 + threadIdx.x;
    int p  = i & (HW - 1);
    int bc = i >> 14;
    int y = p >> 7, xx = p & 127;
    const float* ip = x + (size_t)bc * 65536 + (size_t)(y * 2) * 256 + xx * 2;
    out[i] = fmaxf(fmaxf(ip[0], ip[1]), fmaxf(ip[256], ip[257]));
}

// ---------------- BN stats: one block (512 thr) per channel ----------------
__global__ void k_bnstats(const float* __restrict__ x, const float* __restrict__ gg,
                          const float* __restrict__ bb, int Cc, int slot) {
    int c = blockIdx.x;
    int tid = threadIdx.x;
    const float4* x0 = reinterpret_cast<const float4*>(x + (size_t)c * HW);
    const float4* x1 = reinterpret_cast<const float4*>(x + (size_t)(Cc + c) * HW);
    float s = 0.f, s2 = 0.f;
    for (int p = tid; p < HW / 4; p += 512) {
        float4 a = x0[p];
        s += a.x + a.y + a.z + a.w;
        s2 = fmaf(a.x, a.x, fmaf(a.y, a.y, fmaf(a.z, a.z, fmaf(a.w, a.w, s2))));
        float4 d = x1[p];
        s += d.x + d.y + d.z + d.w;
        s2 = fmaf(d.x, d.x, fmaf(d.y, d.y, fmaf(d.z, d.z, fmaf(d.w, d.w, s2))));
    }
    __shared__ double rs[512], rq[512];
    rs[tid] = (double)s; rq[tid] = (double)s2;
    __syncthreads();
    for (int off = 256; off > 0; off >>= 1) {
        if (tid < off) { rs[tid] += rs[tid + off]; rq[tid] += rq[tid + off]; }
        __syncthreads();
    }
    if (tid == 0) {
        double mean = rs[0] / (double)NPIX;
        double var  = rq[0] / (double)NPIX - mean * mean;
        double A    = (double)gg[c] / sqrt(var + (double)BN_EPS);
        g_A[slot * 128 + c]  = (float)A;
        g_Bv[slot * 128 + c] = (float)((double)bb[c] - mean * A);
    }
}

// ---------------- direct 3x3 conv, pad=1, fused BN+ReLU on input ----------------
// 1D block of 256 threads; tile 32(w) x 64(h) px; 8 co x (2x4) px per thread.
// All 8-co weights preloaded to smem; input channels staged 4 at a time.
template <int CIN>
__launch_bounds__(256, 2)
__global__ void k_conv3(const float* __restrict__ in, const float* __restrict__ w,
                        float* __restrict__ out, int slot) {
    extern __shared__ float sm[];
    float* s_w  = sm;                       // [CIN*72]  layout: ci*72 + k*9 + q
    float* s_in = sm + CIN * 72;            // [4][66*34]
    const int SIN = 66 * 34;                // 2244
    int tid = threadIdx.x;
    int tx = tid & 15, ty = tid >> 4;
    int bz = blockIdx.z;
    int b = bz >> 4, co0 = (bz & 15) * 8;
    int x0 = blockIdx.x * 32, y0 = blockIdx.y * 64;

    for (int i = tid; i < CIN * 72; i += 256) {
        int ci = i / 72, r = i - ci * 72;
        int k = r / 9, q = r - k * 9;
        s_w[i] = w[((size_t)(co0 + k) * CIN + ci) * 9 + q];
    }
    const float* Ap = g_A  + slot * 128;
    const float* Bp = g_Bv + slot * 128;

    float acc[8][8];
#pragma unroll
    for (int k = 0; k < 8; k++)
#pragma unroll
        for (int e = 0; e < 8; e++) acc[k][e] = 0.f;

    int sx = tx * 2, sy = ty * 4;

    for (int c0 = 0; c0 < CIN; c0 += 4) {
        __syncthreads();
        for (int i = tid; i < 4 * SIN; i += 256) {
            int cc = i / SIN, r = i - cc * SIN;
            int iy = r / 34, ix = r - iy * 34;
            int gy = y0 + iy - 1, gx = x0 + ix - 1;
            int ci = c0 + cc;
            float v = 0.f;
            if ((unsigned)gy < 128u && (unsigned)gx < 128u) {
                v = in[((size_t)(b * CIN) + ci) * HW + gy * 128 + gx];
                v = fmaxf(fmaf(v, Ap[ci], Bp[ci]), 0.f);
            }
            s_in[cc * SIN + r] = v;
        }
        __syncthreads();
#pragma unroll 1
        for (int cc = 0; cc < 4; cc++) {
            const float* si = s_in + cc * SIN;
            const float* sw = s_w + (size_t)(c0 + cc) * 72;
#pragma unroll
            for (int dy = 0; dy < 3; dy++)
#pragma unroll
            for (int dx = 0; dx < 3; dx++) {
                float iv[8];
#pragma unroll
                for (int py = 0; py < 4; py++) {
                    iv[py * 2]     = si[(sy + py + dy) * 34 + sx + dx];
                    iv[py * 2 + 1] = si[(sy + py + dy) * 34 + sx + dx + 1];
                }
#pragma unroll
                for (int k = 0; k < 8; k++) {
                    float wv = sw[k * 9 + dy * 3 + dx];
#pragma unroll
                    for (int e = 0; e < 8; e++)
                        acc[k][e] = fmaf(iv[e], wv, acc[k][e]);
                }
            }
        }
    }
#pragma unroll
    for (int k = 0; k < 8; k++) {
        float* op = out + (size_t)(b * C1 + co0 + k) * HW;
#pragma unroll
        for (int py = 0; py < 4; py++) {
            float2 r2 = make_float2(acc[k][py * 2], acc[k][py * 2 + 1]);
            *reinterpret_cast<float2*>(op + (y0 + sy + py) * 128 + x0 + sx) = r2;
        }
    }
}

// ---------------- 1x1 conv (pointwise GEMM), fused BN(+ReLU) input, optional add ----------------
// 256 threads; 4 px (float4) x 16 co per thread.
template <int CIN, int BN, int RELU>
__launch_bounds__(256)
__global__ void k_conv1(const float* __restrict__ in, const float* __restrict__ w,
                        float* __restrict__ out, const float* __restrict__ add,
                        int COUT, int slot) {
    __shared__ float s_w[16 * CIN];
    int tid = threadIdx.x;
    int co0 = blockIdx.y * 16;
    for (int i = tid; i < 16 * CIN; i += 256) {
        int k = i / CIN, ci = i - k * CIN;
        s_w[i] = w[(size_t)(co0 + k) * CIN + ci];
    }
    __syncthreads();
    int gq = blockIdx.x * 1024 + tid * 4;
    int b = gq >> 14;
    int p = gq & (HW - 1);
    const float* ip = in + (size_t)b * CIN * HW + p;
    const float* Ap = g_A  + slot * 128;
    const float* Bp = g_Bv + slot * 128;
    float a[16][4];
#pragma unroll
    for (int k = 0; k < 16; k++) { a[k][0]=a[k][1]=a[k][2]=a[k][3]=0.f; }
#pragma unroll 4
    for (int ci = 0; ci < CIN; ci++) {
        float4 xv = *reinterpret_cast<const float4*>(ip + (size_t)ci * HW);
        if (BN) {
            float A = Ap[ci], Bb = Bp[ci];
            xv.x = fmaf(xv.x, A, Bb); xv.y = fmaf(xv.y, A, Bb);
            xv.z = fmaf(xv.z, A, Bb); xv.w = fmaf(xv.w, A, Bb);
            if (RELU) {
                xv.x = fmaxf(xv.x, 0.f); xv.y = fmaxf(xv.y, 0.f);
                xv.z = fmaxf(xv.z, 0.f); xv.w = fmaxf(xv.w, 0.f);
            }
        }
#pragma unroll
        for (int k = 0; k < 16; k++) {
            float wv = s_w[k * CIN + ci];
            a[k][0] = fmaf(xv.x, wv, a[k][0]);
            a[k][1] = fmaf(xv.y, wv, a[k][1]);
            a[k][2] = fmaf(xv.z, wv, a[k][2]);
            a[k][3] = fmaf(xv.w, wv, a[k][3]);
        }
    }
#pragma unroll
    for (int k = 0; k < 16; k++) {
        size_t idx = (size_t)(b * COUT + co0 + k) * HW + p;
        float4 r = make_float4(a[k][0], a[k][1], a[k][2], a[k][3]);
        if (add) {
            float4 ad = *reinterpret_cast<const float4*>(add + idx);
            r.x += ad.x; r.y += ad.y; r.z += ad.z; r.w += ad.w;
        }
        *reinterpret_cast<float4*>(out + idx) = r;
    }
}

// ---------------- depthwise 3x3, pad=1, optional fused BN (no relu) ----------------
template <int BN>
__global__ void k_dw3(const float* __restrict__ in, const float* __restrict__ w,
                      float* __restrict__ out, int slot) {
    int i = blockIdx.x * 256 + threadIdx.x;
    int p  = i & (HW - 1);
    int bc = i >> 14;
    int c  = bc & 127;
    int y = p >> 7, x = p & 127;
    const float* ip = in + (size_t)bc * HW;
    const float* wp = w + c * 9;
    float A = 1.f, Bb = 0.f;
    if (BN) { A = g_A[slot * 128 + c]; Bb = g_Bv[slot * 128 + c]; }
    float s = 0.f;
#pragma unroll
    for (int dy = 0; dy < 3; dy++) {
        int gy = y + dy - 1;
        if ((unsigned)gy >= 128u) continue;
#pragma unroll
        for (int dx = 0; dx < 3; dx++) {
            int gx = x + dx - 1;
            if ((unsigned)gx >= 128u) continue;
            float v = ip[gy * 128 + gx];
            if (BN) v = fmaf(v, A, Bb);
            s = fmaf(v, wp[dy * 3 + dx], s);
        }
    }
    out[i] = s;
}

// ---------------- bilinear downsample k,v: 128x128 -> 16x16 (align_corners) ----------------
__global__ void k_ds(const float* __restrict__ qkv) {
    int i = blockIdx.x * 256 + threadIdx.x;   // over B*256*R2
    int j  = i & 255;
    int oc = (i >> 8) & 255;
    int b  = i >> 16;
    const float* ip = qkv + ((size_t)(b * 384) + 128 + oc) * HW;
    int r = j >> 4, s = j & 15;
    const float step = (float)(127.0 / 15.0);
    float ph = (float)r * step;
    int   lh = min((int)ph, 126);
    float fh = ph - (float)lh;
    float pw = (float)s * step;
    int   lw = min((int)pw, 126);
    float fw = pw - (float)lw;
    const float* p0 = ip + lh * 128 + lw;
    float v00 = p0[0], v01 = p0[1], v10 = p0[128], v11 = p0[129];
    float val = (1.f - fh) * ((1.f - fw) * v00 + fw * v01)
              +        fh  * ((1.f - fw) * v10 + fw * v11);
    float* dst = (oc < 128) ? g_kd : g_vd;
    int cc = oc & 127;
    dst[(size_t)(b * 128 + cc) * R2 + j] = val;
}

// ---------------- fused attention: one thread per query pixel ----------------
__global__ void k_attn(const float* __restrict__ qkv, const float* __restrict__ table,
                       float* __restrict__ outp) {
    extern __shared__ float sm[];
    float* k_s = sm;                 // [256][32]
    float* v_s = sm + R2 * DH;       // [256][32]
    float* t_s = sm + 2 * R2 * DH;   // [961], pre-scaled
    int tid = threadIdx.x;
    int bh  = blockIdx.y;
    int b = bh >> 2, head = bh & 3;
    const float scale = 0.17677669529663687f;   // 32^-0.5
    for (int i = tid; i < R2 * DH; i += 256) {
        int d = i >> 8, j = i & 255;
        k_s[j * DH + d] = g_kd[((size_t)(b * C1) + d * 4 + head) * R2 + j];
        v_s[j * DH + d] = g_vd[((size_t)(b * C1) + d * 4 + head) * R2 + j];
    }
    for (int i = tid; i < 961; i += 256) t_s[i] = table[i * 4 + head] * scale;
    __syncthreads();

    int p = blockIdx.x * 256 + tid;
    float q[DH];
#pragma unroll
    for (int d = 0; d < DH; d++)
        q[d] = qkv[((size_t)(b * 384) + d * 4 + head) * HW + p] * scale;
    int rh = p >> 10;
    int rw = (p >> 3) & 15;
    float l = 0.f;
    float o[DH];
#pragma unroll
    for (int d = 0; d < DH; d++) o[d] = 0.f;

    for (int j = 0; j < 256; j++) {
        int jh = j >> 4, jw = j & 15;
        float bias = t_s[(rh - jh + 15) * 31 + (rw - jw + 15)];
        const float4* k4 = reinterpret_cast<const float4*>(k_s + j * DH);
        float s = bias;
#pragma unroll
        for (int t = 0; t < 8; t++) {
            float4 kv = k4[t];
            s = fmaf(q[4 * t], kv.x, s);
            s = fmaf(q[4 * t + 1], kv.y, s);
            s = fmaf(q[4 * t + 2], kv.z, s);
            s = fmaf(q[4 * t + 3], kv.w, s);
        }
        float e = __expf(s);
        l += e;
        const float4* v4 = reinterpret_cast<const float4*>(v_s + j * DH);
#pragma unroll
        for (int t = 0; t < 8; t++) {
            float4 vv = v4[t];
            o[4 * t]     = fmaf(e, vv.x, o[4 * t]);
            o[4 * t + 1] = fmaf(e, vv.y, o[4 * t + 1]);
            o[4 * t + 2] = fmaf(e, vv.z, o[4 * t + 2]);
            o[4 * t + 3] = fmaf(e, vv.w, o[4 * t + 3]);
        }
    }
    float inv = 1.f / l;
#pragma unroll
    for (int d = 0; d < DH; d++)
        outp[((size_t)(b * C1) + d * 4 + head) * HW + p] = o[d] * inv;
}

// ---------------- host orchestration ----------------
extern "C" void kernel_launch(void* const* d_in, const int* in_sizes, int n_in,
                              void* d_out, int out_size) {
    (void)in_sizes; (void)n_in; (void)out_size;
    const float* x        = (const float*)d_in[0];
    const float* bb_bn1_g = (const float*)d_in[1];
    const float* bb_bn1_b = (const float*)d_in[2];
    const float* bb_conv1 = (const float*)d_in[3];
    const float* bb_bn2_g = (const float*)d_in[4];
    const float* bb_bn2_b = (const float*)d_in[5];
    const float* bb_conv2 = (const float*)d_in[6];
    const float* bb_sbn_g = (const float*)d_in[7];
    const float* bb_sbn_b = (const float*)d_in[8];
    const float* bb_sconv = (const float*)d_in[9];
    const float* tb_bn1_g = (const float*)d_in[10];
    const float* tb_bn1_b = (const float*)d_in[11];
    const float* tb_dwqkv = (const float*)d_in[12];
    const float* tb_pwqkv = (const float*)d_in[13];
    const float* tb_dwout = (const float*)d_in[14];
    const float* tb_pwout = (const float*)d_in[15];
    const float* tb_rel   = (const float*)d_in[16];
    const float* tb_bn2_g = (const float*)d_in[17];
    const float* tb_bn2_b = (const float*)d_in[18];
    const float* tb_mlp   = (const float*)d_in[19];

    void* pv;
    float *pool, *t, *u, *o, *qkv;
    cudaGetSymbolAddress(&pv, g_pool); pool = (float*)pv;
    cudaGetSymbolAddress(&pv, g_t);    t    = (float*)pv;
    cudaGetSymbolAddress(&pv, g_u);    u    = (float*)pv;
    cudaGetSymbolAddress(&pv, g_o);    o    = (float*)pv;
    cudaGetSymbolAddress(&pv, g_qkv);  qkv  = (float*)pv;

    const int SMEM_C3_64  = (64  * 72 + 4 * 66 * 34) * 4;   // 54336
    const int SMEM_C3_128 = (128 * 72 + 4 * 66 * 34) * 4;   // 72768
    const int ATTN_SMEM   = (2 * R2 * DH + 961) * 4;        // 69380
    cudaFuncSetAttribute(k_conv3<64>,  cudaFuncAttributeMaxDynamicSharedMemorySize, SMEM_C3_64);
    cudaFuncSetAttribute(k_conv3<128>, cudaFuncAttributeMaxDynamicSharedMemorySize, SMEM_C3_128);
    cudaFuncSetAttribute(k_attn, cudaFuncAttributeMaxDynamicSharedMemorySize, 71680);

    dim3 cg3(4, 2, 32);   // 32x64 tiles over 128x128, 16 co-groups x 2 batch

    // ---- maxpool ----
    k_maxpool<<<(B * C0 * HW) / 256, 256>>>(x, pool);

    // ---- BasicBlock ----
    k_bnstats<<<C0, 512>>>(pool, bb_bn1_g, bb_bn1_b, C0, 0);
    k_conv3<64><<<cg3, 256, SMEM_C3_64>>>(pool, bb_conv1, u, 0);
    k_bnstats<<<C1, 512>>>(u, bb_bn2_g, bb_bn2_b, C1, 1);
    k_conv3<128><<<cg3, 256, SMEM_C3_128>>>(u, bb_conv2, o, 1);
    k_bnstats<<<C0, 512>>>(pool, bb_sbn_g, bb_sbn_b, C0, 2);
    k_conv1<64, 1, 1><<<dim3(NPIX / 1024, 8), 256>>>(pool, bb_sconv, o, o, 128, 2);

    // ---- 2 x BasicTransBlock (ping-pong residual between o and t) ----
    float* ob = o;
    float* tb = t;
    for (int i = 0; i < 2; i++) {
        k_bnstats<<<C1, 512>>>(ob, tb_bn1_g + i * 128, tb_bn1_b + i * 128, C1, 3);
        k_dw3<1><<<(B * C1 * HW) / 256, 256>>>(ob, tb_dwqkv + (size_t)i * 128 * 9, u, 3);
        k_conv1<128, 0, 0><<<dim3(NPIX / 1024, 24), 256>>>(
            u, tb_pwqkv + (size_t)i * 384 * 128, qkv, nullptr, 384, 0);
        k_ds<<<(B * 256 * R2) / 256, 256>>>(qkv);
        k_attn<<<dim3(HW / 256, B * 4), 256, ATTN_SMEM>>>(
            qkv, tb_rel + (size_t)i * 961 * 4, tb);
        k_dw3<0><<<(B * C1 * HW) / 256, 256>>>(tb, tb_dwout + (size_t)i * 128 * 9, u, 0);
        k_conv1<128, 0, 0><<<dim3(NPIX / 1024, 8), 256>>>(
            u, tb_pwout + (size_t)i * 128 * 128, ob, ob, 128, 0);   // out = a + out
        k_bnstats<<<C1, 512>>>(ob, tb_bn2_g + i * 128, tb_bn2_b + i * 128, C1, 4);
        float* dest = (i == 1) ? (float*)d_out : tb;
        k_conv1<128, 1, 1><<<dim3(NPIX / 1024, 8), 256>>>(
            ob, tb_mlp + (size_t)i * 128 * 128, dest, ob, 128, 4);  // out = h + out
        // swap roles: new residual lives in dest (tb), old tb buffer free
        float* tmp = ob; ob = tb; tb = tmp;
    }
}

// round 3
// speedup vs baseline: 2.2303x; 2.2303x over previous
#include <cuda_runtime.h>
#include <cstdint>

// ---------------- problem constants ----------------
namespace {
constexpr int B    = 2;
constexpr int C0   = 64;
constexpr int C1   = 128;
constexpr int H    = 128, W = 128;
constexpr int HW   = H * W;            // 16384
constexpr int NPIX = B * HW;           // 32768
constexpr int R2   = 256;              // 16x16 reduced K/V
constexpr int DH   = 32;               // dim_head
constexpr float BN_EPS = 1e-5f;
}

// ---------------- scratch (static device, no allocs) ----------------
__device__ float g_pool[B * C0 * HW];
__device__ float g_t   [B * C1 * HW];
__device__ float g_u   [B * C1 * HW];
__device__ float g_o   [B * C1 * HW];
__device__ float g_qkv [B * 3 * C1 * HW];
__device__ float g_kd  [B * C1 * R2];
__device__ float g_vd  [B * C1 * R2];
__device__ float g_A   [8 * 128];
__device__ float g_Bv  [8 * 128];

// ---------------- helpers ----------------
__device__ __forceinline__ unsigned f2tf(float x) {
    unsigned r;
    asm("cvt.rna.tf32.f32 %0, %1;" : "=r"(r) : "f"(x));
    return r;
}
__device__ __forceinline__ void mma8(float c[4], const unsigned a[4], const unsigned b[2]) {
    asm volatile(
        "mma.sync.aligned.m16n8k8.row.col.f32.tf32.tf32.f32 "
        "{%0,%1,%2,%3},{%4,%5,%6,%7},{%8,%9},{%0,%1,%2,%3};"
        : "+f"(c[0]), "+f"(c[1]), "+f"(c[2]), "+f"(c[3])
        : "r"(a[0]), "r"(a[1]), "r"(a[2]), "r"(a[3]), "r"(b[0]), "r"(b[1]));
}

// ---------------- maxpool 2x2 (256x256 -> 128x128) ----------------
__global__ void k_maxpool(const float* __restrict__ x, float* __restrict__ out) {
    int i = blockIdx.x * 256 + threadIdx.x;
    int p  = i & (HW - 1);
    int bc = i >> 14;
    int y = p >> 7, xx = p & 127;
    const float* ip = x + (size_t)bc * 65536 + (size_t)(y * 2) * 256 + xx * 2;
    out[i] = fmaxf(fmaxf(ip[0], ip[1]), fmaxf(ip[256], ip[257]));
}

// ---------------- BN stats: one block (512 thr) per channel ----------------
__global__ void k_bnstats(const float* __restrict__ x, const float* __restrict__ gg,
                          const float* __restrict__ bb, int Cc, int slot) {
    int c = blockIdx.x;
    int tid = threadIdx.x;
    const float4* x0 = reinterpret_cast<const float4*>(x + (size_t)c * HW);
    const float4* x1 = reinterpret_cast<const float4*>(x + (size_t)(Cc + c) * HW);
    float s = 0.f, s2 = 0.f;
    for (int p = tid; p < HW / 4; p += 512) {
        float4 a = x0[p];
        s += a.x + a.y + a.z + a.w;
        s2 = fmaf(a.x, a.x, fmaf(a.y, a.y, fmaf(a.z, a.z, fmaf(a.w, a.w, s2))));
        float4 d = x1[p];
        s += d.x + d.y + d.z + d.w;
        s2 = fmaf(d.x, d.x, fmaf(d.y, d.y, fmaf(d.z, d.z, fmaf(d.w, d.w, s2))));
    }
    __shared__ double rs[512], rq[512];
    rs[tid] = (double)s; rq[tid] = (double)s2;
    __syncthreads();
    for (int off = 256; off > 0; off >>= 1) {
        if (tid < off) { rs[tid] += rs[tid + off]; rq[tid] += rq[tid + off]; }
        __syncthreads();
    }
    if (tid == 0) {
        double mean = rs[0] / (double)NPIX;
        double var  = rq[0] / (double)NPIX - mean * mean;
        double A    = (double)gg[c] / sqrt(var + (double)BN_EPS);
        g_A[slot * 128 + c]  = (float)A;
        g_Bv[slot * 128 + c] = (float)((double)bb[c] - mean * A);
    }
}

// ---------------- tf32 GEMM: C[M,N] = W[M,K] @ X[K,N] (+add), N = pixel axis ----------
// Block tile 128(M) x 128(N), 256 threads = 8 warps (2x4: wm=64, wn=32), K-chunk 32.
// IC: X is implicit im2col of a CIN-channel 128x128 image (K = CIN*9), zero padding.
// BN/RELU applied to X elements before the GEMM (matches conv(relu(bn(x))) with
// zero-padding applied AFTER the activation). ADD: out = C + add.
template <int K, int CIN, bool IC, bool BN, bool RELU, bool ADD>
__global__ __launch_bounds__(256)
void k_gemm(const float* __restrict__ in, const float* __restrict__ w,
            float* __restrict__ out, const float* __restrict__ add,
            int COUT, int slot) {
    __shared__ unsigned sA[128 * 36];     // [row][k] stride 36
    __shared__ unsigned sB[32 * 136];     // [k][n]  stride 136

    const int tid = threadIdx.x;
    const int lane = tid & 31, warp = tid >> 5;
    const int gid = lane >> 2, qid = lane & 3;
    const int wm = (warp & 1) * 64, wn = (warp >> 1) * 32;

    const int n0 = blockIdx.x * 128;
    const int m0 = blockIdx.y * 128;
    const int b  = n0 >> 14;
    const int pbase = n0 & (HW - 1);
    const int y = pbase >> 7;             // image row (n-tile spans one row)

    const float* Ap = g_A  + slot * 128;
    const float* Bp = g_Bv + slot * 128;

    float c[4][4][4];
#pragma unroll
    for (int mt = 0; mt < 4; mt++)
#pragma unroll
        for (int nt = 0; nt < 4; nt++)
#pragma unroll
            for (int e = 0; e < 4; e++) c[mt][nt][e] = 0.f;

    // loader index precompute
    const int a_col4 = (tid & 7) * 4;     // A: 8 col-groups x 4
    const int a_row0 = tid >> 3;          // 32 rows per pass, 4 passes
    const int b_col4 = (tid & 31) * 4;    // B: 32 col-groups x 4
    const int b_row0 = tid >> 5;          // 8 rows per pass, 4 passes

    for (int k0 = 0; k0 < K; k0 += 32) {
        __syncthreads();
        // ---- stage A (weights) ----
#pragma unroll
        for (int i = 0; i < 4; i++) {
            int row = a_row0 + 32 * i;
            const float4 wv = *reinterpret_cast<const float4*>(
                w + (size_t)(m0 + row) * K + k0 + a_col4);
            unsigned* d = sA + row * 36 + a_col4;
            d[0] = f2tf(wv.x); d[1] = f2tf(wv.y); d[2] = f2tf(wv.z); d[3] = f2tf(wv.w);
        }
        // ---- stage B (input / implicit im2col) ----
#pragma unroll
        for (int i = 0; i < 4; i++) {
            int r = b_row0 + 8 * i;
            int k = k0 + r;
            unsigned* d = sB + r * 136 + b_col4;
            if (IC) {
                int ci = k / 9, q = k - ci * 9;
                int dy = q / 3 - 1, dx = q - (q / 3) * 3 - 1;
                int gy = y + dy;
                float A = 1.f, Bb = 0.f;
                if (BN) { A = Ap[ci]; Bb = Bp[ci]; }
                const float* src = in + ((size_t)(b * CIN) + ci) * HW + gy * 128;
                bool yok = (unsigned)gy < 128u;
#pragma unroll
                for (int e = 0; e < 4; e++) {
                    int gx = b_col4 + dx + e;
                    float v = 0.f;
                    if (yok && (unsigned)gx < 128u) {
                        v = src[gx];
                        if (BN) v = fmaf(v, A, Bb);
                        if (RELU) v = fmaxf(v, 0.f);
                    }
                    d[e] = f2tf(v);
                }
            } else {
                float4 xv = *reinterpret_cast<const float4*>(
                    in + ((size_t)(b * CIN) + k) * HW + pbase + b_col4);
                if (BN) {
                    float A = Ap[k], Bb = Bp[k];
                    xv.x = fmaf(xv.x, A, Bb); xv.y = fmaf(xv.y, A, Bb);
                    xv.z = fmaf(xv.z, A, Bb); xv.w = fmaf(xv.w, A, Bb);
                    if (RELU) {
                        xv.x = fmaxf(xv.x, 0.f); xv.y = fmaxf(xv.y, 0.f);
                        xv.z = fmaxf(xv.z, 0.f); xv.w = fmaxf(xv.w, 0.f);
                    }
                }
                d[0] = f2tf(xv.x); d[1] = f2tf(xv.y); d[2] = f2tf(xv.z); d[3] = f2tf(xv.w);
            }
        }
        __syncthreads();
        // ---- 4 k-steps of mma ----
#pragma unroll
        for (int ks = 0; ks < 4; ks++) {
            const int kk = ks * 8;
            unsigned af[4][4], bf[4][2];
#pragma unroll
            for (int mt = 0; mt < 4; mt++) {
                const unsigned* sa = sA + (wm + mt * 16 + gid) * 36 + kk + qid;
                af[mt][0] = sa[0];
                af[mt][1] = sa[8 * 36];
                af[mt][2] = sa[4];
                af[mt][3] = sa[8 * 36 + 4];
            }
#pragma unroll
            for (int nt = 0; nt < 4; nt++) {
                const unsigned* sb = sB + (kk + qid) * 136 + wn + nt * 8 + gid;
                bf[nt][0] = sb[0];
                bf[nt][1] = sb[4 * 136];
            }
#pragma unroll
            for (int mt = 0; mt < 4; mt++)
#pragma unroll
                for (int nt = 0; nt < 4; nt++)
                    mma8(c[mt][nt], af[mt], bf[nt]);
        }
    }

    // ---- epilogue ----
#pragma unroll
    for (int mt = 0; mt < 4; mt++) {
        int co = m0 + wm + mt * 16 + gid;
#pragma unroll
        for (int nt = 0; nt < 4; nt++) {
            int cb = wn + nt * 8 + qid * 2;
            size_t idx0 = ((size_t)(b * COUT) + co) * HW + pbase + cb;
            size_t idx1 = ((size_t)(b * COUT) + co + 8) * HW + pbase + cb;
            float2 r0 = make_float2(c[mt][nt][0], c[mt][nt][1]);
            float2 r1 = make_float2(c[mt][nt][2], c[mt][nt][3]);
            if (ADD) {
                float2 a0 = *reinterpret_cast<const float2*>(add + idx0);
                float2 a1 = *reinterpret_cast<const float2*>(add + idx1);
                r0.x += a0.x; r0.y += a0.y; r1.x += a1.x; r1.y += a1.y;
            }
            *reinterpret_cast<float2*>(out + idx0) = r0;
            *reinterpret_cast<float2*>(out + idx1) = r1;
        }
    }
}

// ---------------- depthwise 3x3, pad=1, optional fused BN ----------------
template <int BN>
__global__ void k_dw3(const float* __restrict__ in, const float* __restrict__ w,
                      float* __restrict__ out, int slot) {
    int i = blockIdx.x * 256 + threadIdx.x;
    int p  = i & (HW - 1);
    int bc = i >> 14;
    int c  = bc & 127;
    int y = p >> 7, x = p & 127;
    const float* ip = in + (size_t)bc * HW;
    const float* wp = w + c * 9;
    float A = 1.f, Bb = 0.f;
    if (BN) { A = g_A[slot * 128 + c]; Bb = g_Bv[slot * 128 + c]; }
    float s = 0.f;
#pragma unroll
    for (int dy = 0; dy < 3; dy++) {
        int gy = y + dy - 1;
        if ((unsigned)gy >= 128u) continue;
#pragma unroll
        for (int dx = 0; dx < 3; dx++) {
            int gx = x + dx - 1;
            if ((unsigned)gx >= 128u) continue;
            float v = ip[gy * 128 + gx];
            if (BN) v = fmaf(v, A, Bb);
            s = fmaf(v, wp[dy * 3 + dx], s);
        }
    }
    out[i] = s;
}

// ---------------- bilinear downsample k,v: 128x128 -> 16x16 (align_corners) ----------------
__global__ void k_ds(const float* __restrict__ qkv) {
    int i = blockIdx.x * 256 + threadIdx.x;
    int j  = i & 255;
    int oc = (i >> 8) & 255;
    int b  = i >> 16;
    const float* ip = qkv + ((size_t)(b * 384) + 128 + oc) * HW;
    int r = j >> 4, s = j & 15;
    const float step = (float)(127.0 / 15.0);
    float ph = (float)r * step;
    int   lh = min((int)ph, 126);
    float fh = ph - (float)lh;
    float pw = (float)s * step;
    int   lw = min((int)pw, 126);
    float fw = pw - (float)lw;
    const float* p0 = ip + lh * 128 + lw;
    float v00 = p0[0], v01 = p0[1], v10 = p0[128], v11 = p0[129];
    float val = (1.f - fh) * ((1.f - fw) * v00 + fw * v01)
              +        fh  * ((1.f - fw) * v10 + fw * v11);
    float* dst = (oc < 128) ? g_kd : g_vd;
    int cc = oc & 127;
    dst[(size_t)(b * 128 + cc) * R2 + j] = val;
}

// ---------------- fused attention: one thread per query pixel ----------------
__global__ void k_attn(const float* __restrict__ qkv, const float* __restrict__ table,
                       float* __restrict__ outp) {
    extern __shared__ float sm[];
    float* k_s = sm;
    float* v_s = sm + R2 * DH;
    float* t_s = sm + 2 * R2 * DH;
    int tid = threadIdx.x;
    int bh  = blockIdx.y;
    int b = bh >> 2, head = bh & 3;
    const float scale = 0.17677669529663687f;
    for (int i = tid; i < R2 * DH; i += 256) {
        int d = i >> 8, j = i & 255;
        k_s[j * DH + d] = g_kd[((size_t)(b * C1) + d * 4 + head) * R2 + j];
        v_s[j * DH + d] = g_vd[((size_t)(b * C1) + d * 4 + head) * R2 + j];
    }
    for (int i = tid; i < 961; i += 256) t_s[i] = table[i * 4 + head] * scale;
    __syncthreads();

    int p = blockIdx.x * 256 + tid;
    float q[DH];
#pragma unroll
    for (int d = 0; d < DH; d++)
        q[d] = qkv[((size_t)(b * 384) + d * 4 + head) * HW + p] * scale;
    int rh = p >> 10;
    int rw = (p >> 3) & 15;
    float l = 0.f;
    float o[DH];
#pragma unroll
    for (int d = 0; d < DH; d++) o[d] = 0.f;

    for (int j = 0; j < 256; j++) {
        int jh = j >> 4, jw = j & 15;
        float bias = t_s[(rh - jh + 15) * 31 + (rw - jw + 15)];
        const float4* k4 = reinterpret_cast<const float4*>(k_s + j * DH);
        float s = bias;
#pragma unroll
        for (int t = 0; t < 8; t++) {
            float4 kv = k4[t];
            s = fmaf(q[4 * t], kv.x, s);
            s = fmaf(q[4 * t + 1], kv.y, s);
            s = fmaf(q[4 * t + 2], kv.z, s);
            s = fmaf(q[4 * t + 3], kv.w, s);
        }
        float e = __expf(s);
        l += e;
        const float4* v4 = reinterpret_cast<const float4*>(v_s + j * DH);
#pragma unroll
        for (int t = 0; t < 8; t++) {
            float4 vv = v4[t];
            o[4 * t]     = fmaf(e, vv.x, o[4 * t]);
            o[4 * t + 1] = fmaf(e, vv.y, o[4 * t + 1]);
            o[4 * t + 2] = fmaf(e, vv.z, o[4 * t + 2]);
            o[4 * t + 3] = fmaf(e, vv.w, o[4 * t + 3]);
        }
    }
    float inv = 1.f / l;
#pragma unroll
    for (int d = 0; d < DH; d++)
        outp[((size_t)(b * C1) + d * 4 + head) * HW + p] = o[d] * inv;
}

// ---------------- host orchestration ----------------
extern "C" void kernel_launch(void* const* d_in, const int* in_sizes, int n_in,
                              void* d_out, int out_size) {
    (void)in_sizes; (void)n_in; (void)out_size;
    const float* x        = (const float*)d_in[0];
    const float* bb_bn1_g = (const float*)d_in[1];
    const float* bb_bn1_b = (const float*)d_in[2];
    const float* bb_conv1 = (const float*)d_in[3];
    const float* bb_bn2_g = (const float*)d_in[4];
    const float* bb_bn2_b = (const float*)d_in[5];
    const float* bb_conv2 = (const float*)d_in[6];
    const float* bb_sbn_g = (const float*)d_in[7];
    const float* bb_sbn_b = (const float*)d_in[8];
    const float* bb_sconv = (const float*)d_in[9];
    const float* tb_bn1_g = (const float*)d_in[10];
    const float* tb_bn1_b = (const float*)d_in[11];
    const float* tb_dwqkv = (const float*)d_in[12];
    const float* tb_pwqkv = (const float*)d_in[13];
    const float* tb_dwout = (const float*)d_in[14];
    const float* tb_pwout = (const float*)d_in[15];
    const float* tb_rel   = (const float*)d_in[16];
    const float* tb_bn2_g = (const float*)d_in[17];
    const float* tb_bn2_b = (const float*)d_in[18];
    const float* tb_mlp   = (const float*)d_in[19];

    void* pv;
    float *pool, *t, *u, *o, *qkv;
    cudaGetSymbolAddress(&pv, g_pool); pool = (float*)pv;
    cudaGetSymbolAddress(&pv, g_t);    t    = (float*)pv;
    cudaGetSymbolAddress(&pv, g_u);    u    = (float*)pv;
    cudaGetSymbolAddress(&pv, g_o);    o    = (float*)pv;
    cudaGetSymbolAddress(&pv, g_qkv);  qkv  = (float*)pv;

    const int ATTN_SMEM = (2 * R2 * DH + 961) * 4;
    cudaFuncSetAttribute(k_attn, cudaFuncAttributeMaxDynamicSharedMemorySize, 71680);

    const dim3 g1(NPIX / 128, 1);   // M=128 GEMMs
    const dim3 g3(NPIX / 128, 3);   // M=384 GEMM (qkv)

    // ---- maxpool ----
    k_maxpool<<<(B * C0 * HW) / 256, 256>>>(x, pool);

    // ---- BasicBlock ----
    k_bnstats<<<C0, 512>>>(pool, bb_bn1_g, bb_bn1_b, C0, 0);
    k_gemm<576, 64, true, true, true, false><<<g1, 256>>>(pool, bb_conv1, u, nullptr, 128, 0);
    k_bnstats<<<C1, 512>>>(u, bb_bn2_g, bb_bn2_b, C1, 1);
    k_gemm<1152, 128, true, true, true, false><<<g1, 256>>>(u, bb_conv2, o, nullptr, 128, 1);
    k_bnstats<<<C0, 512>>>(pool, bb_sbn_g, bb_sbn_b, C0, 2);
    k_gemm<64, 64, false, true, true, true><<<g1, 256>>>(pool, bb_sconv, o, o, 128, 2);

    // ---- 2 x BasicTransBlock (ping-pong residual between o and t) ----
    float* ob = o;
    float* tb = t;
    for (int i = 0; i < 2; i++) {
        k_bnstats<<<C1, 512>>>(ob, tb_bn1_g + i * 128, tb_bn1_b + i * 128, C1, 3);
        k_dw3<1><<<(B * C1 * HW) / 256, 256>>>(ob, tb_dwqkv + (size_t)i * 128 * 9, u, 3);
        k_gemm<128, 128, false, false, false, false><<<g3, 256>>>(
            u, tb_pwqkv + (size_t)i * 384 * 128, qkv, nullptr, 384, 0);
        k_ds<<<(B * 256 * R2) / 256, 256>>>(qkv);
        k_attn<<<dim3(HW / 256, B * 4), 256, ATTN_SMEM>>>(
            qkv, tb_rel + (size_t)i * 961 * 4, tb);
        k_dw3<0><<<(B * C1 * HW) / 256, 256>>>(tb, tb_dwout + (size_t)i * 128 * 9, u, 0);
        k_gemm<128, 128, false, false, false, true><<<g1, 256>>>(
            u, tb_pwout + (size_t)i * 128 * 128, ob, ob, 128, 0);
        k_bnstats<<<C1, 512>>>(ob, tb_bn2_g + i * 128, tb_bn2_b + i * 128, C1, 4);
        float* dest = (i == 1) ? (float*)d_out : tb;
        k_gemm<128, 128, false, true, true, true><<<g1, 256>>>(
            ob, tb_mlp + (size_t)i * 128 * 128, dest, ob, 128, 4);
        float* tmp = ob; ob = tb; tb = tmp;
    }
}